// round 11
// baseline (speedup 1.0000x reference)
#include <cuda_runtime.h>

#define BB 8
#define CC 256
#define HH 96
#define WW 96
#define HW (HH*WW)          // 9216
#define PATCH 21
#define NP    (PATCH*PATCH) // 441
#define HALFP 10
#define DILP 2
#define TROW 136            // 96 + 2*20 halo

#define NDOT  576           // dot units: 128 spatial floats x 256ch each
#define NGATH 768           // gather units: (b,y), batch-major
#define NPROD 288           // producer blocks (2 dot units each, exact)
#define NCONS 304           // consumer blocks
#define GRID  (NPROD + NCONS)   // 592 = 148*4, all resident at occ 4

#define NHELP 96            // producer blocks that take the 96 batch-7 gathers
#define GSPLIT (NGATH - NHELP)  // 672: consumers take units [0,672)
#define NRESET (NCONS + NHELP)  // blocks that read g_cnt -> gate the reset

__device__ float g_D[BB * HW];     // 1.18 MB, L2-resident
__device__ int   g_cnt[BB];        // per-batch completed dot units (target 72)
__device__ int   g_done;           // finished g_cnt-readers (self-reset gate)

union SM {
    float4 red[256];
    float  tile[PATCH * TROW];   // 11424 B
};

// One gather unit: stage 21 source rows into a zero-padded smem tile, then
// stream out 441 x 24 float4 for this (bb, y). Proven R3/R5/R8 body.
__device__ __forceinline__ void do_gather(SM& sm, int g, int tid,
                                          float* __restrict__ out) {
    const float4* __restrict__ D4 = (const float4*)g_D;
    float4* __restrict__ O4 = (float4*)out;

    const int bb = g / HH;
    const int y  = g - bb * HH;

    // zero tile while (possibly) waiting
    for (int i = tid; i < PATCH * TROW; i += 256) sm.tile[i] = 0.f;

    if (tid == 0) {
        volatile int* c = &g_cnt[bb];
        while (*c < 72) __nanosleep(100);
        __threadfence();                   // acquire
    }
    __syncthreads();

    for (int i = tid; i < PATCH * 24; i += 256) {
        const int r  = i / 24;
        const int x4 = i - r * 24;
        const int sy = y + (r - HALFP) * DILP;
        if ((unsigned)sy < (unsigned)HH) {
            float4 v = D4[(bb * HH + sy) * 24 + x4];
            *(float4*)(sm.tile + r * TROW + 20 + x4 * 4) = v;
        }
    }
    __syncthreads();

    const size_t obase = ((size_t)bb * NP) * (HW / 4) + y * 24;
    for (int i = tid; i < NP * 24; i += 256) {
        const int p  = i / 24;
        const int x4 = i - p * 24;
        const int py = p / PATCH;
        const int px = p - py * PATCH;

        const float2* sp =
            (const float2*)(sm.tile + py * TROW + px * 2 + x4 * 4);
        float2 lo = sp[0];
        float2 hi = sp[1];

        O4[obase + (size_t)p * (HW / 4) + x4] =
            make_float4(lo.x, lo.y, hi.x, hi.y);
    }
    __syncthreads();                       // tile reuse safety
}

// Self-clean gate: every block that READ g_cnt must pass through here; the
// last such block resets sync state for the next graph replay.
__device__ __forceinline__ void reset_gate(int tid) {
    if (tid == 0) {
        __threadfence();
        int d = atomicAdd(&g_done, 1);
        if (d == NRESET - 1) {
            #pragma unroll
            for (int i = 0; i < BB; ++i) g_cnt[i] = 0;
            g_done = 0;
            __threadfence();
        }
    }
}

__global__ void __launch_bounds__(256, 4) fused_kernel(
        const float* __restrict__ a,
        const float* __restrict__ b,
        float* __restrict__ out) {
    __shared__ SM sm;

    const int tid = threadIdx.x;
    const int bid = blockIdx.x;

    if (bid < NPROD) {
        // ===================== PRODUCER: dot units =====================
        const int lane = tid & 31;
        const int cg   = tid >> 5;
        const int cstride = HW / 4;
        const int c0 = cg * 32;

        for (int u = bid; u < NDOT; u += NPROD) {
            const int bidx = u / 72;                   // batch
            const int hw   = ((u * 128) % HW) + lane * 4;

            const float4* __restrict__ A =
                (const float4*)(a + (size_t)bidx * CC * HW + hw);
            const float4* __restrict__ Bp =
                (const float4*)(b + (size_t)bidx * CC * HW + hw);

            float4 acc = make_float4(0.f, 0.f, 0.f, 0.f);
            #pragma unroll 8
            for (int c = 0; c < 32; ++c) {
                const size_t off = (size_t)(c0 + c) * cstride;
                float4 x = A[off];
                float4 y = Bp[off];
                acc.x = fmaf(x.x, y.x, acc.x);
                acc.y = fmaf(x.y, y.y, acc.y);
                acc.z = fmaf(x.z, y.z, acc.z);
                acc.w = fmaf(x.w, y.w, acc.w);
            }

            sm.red[tid] = acc;
            __syncthreads();
            if (tid < 32) {
                float4 r = sm.red[tid];
                #pragma unroll
                for (int k = 1; k < 8; ++k) {
                    float4 t = sm.red[tid + 32 * k];
                    r.x += t.x; r.y += t.y; r.z += t.z; r.w += t.w;
                }
                ((float4*)g_D)[(size_t)u * 32 + tid] = r;
            }
            __syncthreads();                       // reduce done, smem free
            if (tid == 0) {
                __threadfence();                   // publish g_D
                atomicAdd(&g_cnt[bidx], 1);
            }
        }

        // ---- tail help: first NHELP producers each take one batch-7
        // gather unit (static mapping; units [GSPLIT, NGATH)). These units
        // cannot start before the producer phase ends anyway.
        if (bid < NHELP) {
            __syncthreads();               // smem handoff to tile use
            do_gather(sm, GSPLIT + bid, tid, out);
            reset_gate(tid);
        }
    } else {
        // ===================== CONSUMER: gather units =====================
        for (int g = bid - NPROD; g < GSPLIT; g += NCONS)
            do_gather(sm, g, tid, out);
        reset_gate(tid);
    }
}

extern "C" void kernel_launch(void* const* d_in, const int* in_sizes, int n_in,
                              void* d_out, int out_size) {
    const float* in1 = (const float*)d_in[0];
    const float* in2 = (const float*)d_in[1];
    float* out = (float*)d_out;

    fused_kernel<<<GRID, 256>>>(in1, in2, out);
}

// round 12
// speedup vs baseline: 1.1462x; 1.1462x over previous
#include <cuda_runtime.h>
#include <cstdint>

#define BB 8
#define CC 256
#define HH 96
#define WW 96
#define HW (HH*WW)          // 9216
#define PATCH 21
#define NP    (PATCH*PATCH) // 441
#define HALFP 10
#define DILP 2
#define TROW 136            // 96 + 2*20 halo

#define NDOT  576           // dot units: 128 spatial floats x 256ch each
#define NGATH 768           // gather units: (b,y)
#define NPROD 288           // producer blocks
#define NCONS 304           // consumer blocks
#define GRID  (NPROD + NCONS)   // 592 = 148*4, all resident at occ 4

__device__ float g_D[BB * HW];     // 1.18 MB, L2-resident
__device__ int   g_cnt[BB];        // per-batch completed dot units (target 72)
__device__ int   g_done;           // finished consumer blocks (self-reset)

// 32B store, L2 evict_first: output is write-once and dead after the replay;
// keep it from evicting the cross-replay-resident input set.
__device__ __forceinline__ void st8_first(float* p, float4 a, float4 b) {
    asm volatile("st.global.L2::evict_first.v8.b32 [%0], {%1,%2,%3,%4,%5,%6,%7,%8};"
        :: "l"(p),
           "r"(__float_as_uint(a.x)), "r"(__float_as_uint(a.y)),
           "r"(__float_as_uint(a.z)), "r"(__float_as_uint(a.w)),
           "r"(__float_as_uint(b.x)), "r"(__float_as_uint(b.y)),
           "r"(__float_as_uint(b.z)), "r"(__float_as_uint(b.w)) : "memory");
}

__global__ void __launch_bounds__(256, 4) fused_kernel(
        const float* __restrict__ a,
        const float* __restrict__ b,
        float* __restrict__ out) {
    __shared__ union {
        float4 red[256];
        float  tile[PATCH * TROW];   // 11424 B
    } sm;

    const int tid = threadIdx.x;
    const int bid = blockIdx.x;

    if (bid < NPROD) {
        // ===================== PRODUCER: dot units (exact R8) ==============
        const int lane = tid & 31;
        const int cg   = tid >> 5;
        const int cstride = HW / 4;
        const int c0 = cg * 32;

        for (int u = bid; u < NDOT; u += NPROD) {
            const int sbase = u * 128;
            const int bidx  = u / 72;                  // batch
            const int hw    = (sbase % HW) + lane * 4;

            const float4* __restrict__ A =
                (const float4*)(a + (size_t)bidx * CC * HW + hw);
            const float4* __restrict__ Bp =
                (const float4*)(b + (size_t)bidx * CC * HW + hw);

            float4 acc = make_float4(0.f, 0.f, 0.f, 0.f);
            #pragma unroll 4
            for (int c = 0; c < 32; ++c) {
                const size_t off = (size_t)(c0 + c) * cstride;
                float4 x = A[off];
                float4 y = Bp[off];
                acc.x = fmaf(x.x, y.x, acc.x);
                acc.y = fmaf(x.y, y.y, acc.y);
                acc.z = fmaf(x.z, y.z, acc.z);
                acc.w = fmaf(x.w, y.w, acc.w);
            }

            sm.red[tid] = acc;
            __syncthreads();
            if (tid < 32) {
                float4 r = sm.red[tid];
                #pragma unroll
                for (int k = 1; k < 8; ++k) {
                    float4 t = sm.red[tid + 32 * k];
                    r.x += t.x; r.y += t.y; r.z += t.z; r.w += t.w;
                }
                ((float4*)g_D)[(size_t)u * 32 + tid] = r;
            }
            __syncthreads();                       // reduce done, smem free
            if (tid == 0) {
                __threadfence();                   // publish g_D
                atomicAdd(&g_cnt[bidx], 1);
            }
        }
    } else {
        // ===================== CONSUMER: gather units ======================
        const float4* __restrict__ D4 = (const float4*)g_D;

        for (int g = bid - NPROD; g < NGATH; g += NCONS) {
            const int bb = g / HH;                 // batch
            const int y  = g - bb * HH;

            // zero tile while (possibly) waiting
            for (int i = tid; i < PATCH * TROW; i += 256) sm.tile[i] = 0.f;

            if (tid == 0) {
                volatile int* c = &g_cnt[bb];
                while (*c < 72) __nanosleep(100);
                __threadfence();                   // acquire
            }
            __syncthreads();

            // stage 21 candidate rows (+-20 col halo pre-zeroed)
            for (int i = tid; i < PATCH * 24; i += 256) {
                const int r  = i / 24;
                const int x4 = i - r * 24;
                const int sy = y + (r - HALFP) * DILP;
                if ((unsigned)sy < (unsigned)HH) {
                    float4 v = D4[(bb * HH + sy) * 24 + x4];
                    *(float4*)(sm.tile + r * TROW + 20 + x4 * 4) = v;
                }
            }
            __syncthreads();

            // emit 441 x 12 32B evict-first stores (only change vs R8)
            float* obase = out + ((size_t)bb * NP) * HW + y * WW;
            for (int i = tid; i < NP * 12; i += 256) {
                const int p  = i / 12;
                const int x8 = i - p * 12;
                const int py = p / PATCH;
                const int px = p - py * PATCH;

                const float2* sp =
                    (const float2*)(sm.tile + py * TROW + px * 2 + x8 * 8);
                float2 q0 = sp[0], q1 = sp[1], q2 = sp[2], q3 = sp[3];

                st8_first(obase + (size_t)p * HW + x8 * 8,
                          make_float4(q0.x, q0.y, q1.x, q1.y),
                          make_float4(q2.x, q2.y, q3.x, q3.y));
            }
            __syncthreads();                       // tile reuse safety
        }

        // ---- self-clean: last consumer block resets sync state for the
        // next graph replay (proven in R6/R8).
        if (tid == 0) {
            __threadfence();
            int d = atomicAdd(&g_done, 1);
            if (d == NCONS - 1) {
                #pragma unroll
                for (int i = 0; i < BB; ++i) g_cnt[i] = 0;
                g_done = 0;
                __threadfence();
            }
        }
    }
}

extern "C" void kernel_launch(void* const* d_in, const int* in_sizes, int n_in,
                              void* d_out, int out_size) {
    const float* in1 = (const float*)d_in[0];
    const float* in2 = (const float*)d_in[1];
    float* out = (float*)d_out;

    fused_kernel<<<GRID, 256>>>(in1, in2, out);
}